// round 1
// baseline (speedup 1.0000x reference)
#include <cuda_runtime.h>
#include <math_constants.h>

#define B_  4
#define C_  512
#define HC_ 256
#define N_  4096

// Scratch: f rows [0,256), g rows [256,512), h rows [512,1024), each [row][n]
__device__ float g_fgh[(size_t)B_ * 1024 * N_];
// energy / correlation, [b][j][k]
__device__ float g_E[(size_t)B_ * N_ * N_];

// ---------------------------------------------------------------------------
// GEMM 1: projections.  out[o][n] = sum_c W[o][c] * x[c][n] + bias[o]
// M=1024 (o), N=4096 (n), K=512 (c).  A is K-contiguous, B is N-contiguous.
// ---------------------------------------------------------------------------
__global__ __launch_bounds__(256) void proj_kernel(
    const float* __restrict__ x,
    const float* __restrict__ Wf, const float* __restrict__ bf,
    const float* __restrict__ Wg, const float* __restrict__ bg,
    const float* __restrict__ Wh, const float* __restrict__ bh)
{
    const int b  = blockIdx.z;
    const int n0 = blockIdx.x * 128;
    const int o0 = blockIdx.y * 128;

    const float* W; const float* bias; int off;
    if (o0 < 256)      { W = Wf; bias = bf; off = o0; }
    else if (o0 < 512) { W = Wg; bias = bg; off = o0 - 256; }
    else               { W = Wh; bias = bh; off = o0 - 512; }

    const float* X = x + (size_t)b * C_ * N_;

    __shared__ float As[8][128];   // [k][o]
    __shared__ float Bs[8][128];   // [k][n]

    const int tid = threadIdx.x;
    const int tx = tid & 15, ty = tid >> 4;

    // A load: transpose K-contiguous rows into As
    const int a_r  = tid >> 1;           // 0..127  (o row)
    const int a_k4 = (tid & 1) * 4;      // 0 or 4
    // B load: direct
    const int b_k  = tid >> 5;           // 0..7
    const int b_c4 = (tid & 31) * 4;     // 0..124

    float acc[8][8] = {};

    for (int k0 = 0; k0 < C_; k0 += 8) {
        float4 av = *reinterpret_cast<const float4*>(&W[(size_t)(off + a_r) * C_ + k0 + a_k4]);
        As[a_k4 + 0][a_r] = av.x; As[a_k4 + 1][a_r] = av.y;
        As[a_k4 + 2][a_r] = av.z; As[a_k4 + 3][a_r] = av.w;
        *reinterpret_cast<float4*>(&Bs[b_k][b_c4]) =
            *reinterpret_cast<const float4*>(&X[(size_t)(k0 + b_k) * N_ + n0 + b_c4]);
        __syncthreads();
        #pragma unroll
        for (int kk = 0; kk < 8; ++kk) {
            float a[8], bb[8];
            #pragma unroll
            for (int i = 0; i < 8; ++i) a[i]  = As[kk][ty * 8 + i];
            #pragma unroll
            for (int j = 0; j < 8; ++j) bb[j] = Bs[kk][tx * 8 + j];
            #pragma unroll
            for (int i = 0; i < 8; ++i)
                #pragma unroll
                for (int j = 0; j < 8; ++j)
                    acc[i][j] += a[i] * bb[j];
        }
        __syncthreads();
    }

    float* out = g_fgh + (size_t)b * 1024 * N_;
    #pragma unroll
    for (int i = 0; i < 8; ++i) {
        const float bv = bias[off + ty * 8 + i];
        #pragma unroll
        for (int j = 0; j < 8; ++j)
            out[(size_t)(o0 + ty * 8 + i) * N_ + n0 + tx * 8 + j] = acc[i][j] + bv;
    }
}

// ---------------------------------------------------------------------------
// GEMM 2: energy.  E[j][k] = sum_c f[c][j] * g[c][k]
// Both operands are M/N-contiguous (stride N_ along c) -> direct tile loads.
// ---------------------------------------------------------------------------
__global__ __launch_bounds__(256) void energy_kernel()
{
    const int b  = blockIdx.z;
    const int j0 = blockIdx.y * 128;
    const int k0c = blockIdx.x * 128;

    const float* F = g_fgh + (size_t)b * 1024 * N_;           // rows 0..255
    const float* G = F + (size_t)HC_ * N_;                    // rows 256..511

    __shared__ float As[8][128];
    __shared__ float Bs[8][128];

    const int tid = threadIdx.x;
    const int tx = tid & 15, ty = tid >> 4;
    const int l_k  = tid >> 5;
    const int l_c4 = (tid & 31) * 4;

    float acc[8][8] = {};

    for (int c0 = 0; c0 < HC_; c0 += 8) {
        *reinterpret_cast<float4*>(&As[l_k][l_c4]) =
            *reinterpret_cast<const float4*>(&F[(size_t)(c0 + l_k) * N_ + j0 + l_c4]);
        *reinterpret_cast<float4*>(&Bs[l_k][l_c4]) =
            *reinterpret_cast<const float4*>(&G[(size_t)(c0 + l_k) * N_ + k0c + l_c4]);
        __syncthreads();
        #pragma unroll
        for (int kk = 0; kk < 8; ++kk) {
            float a[8], bb[8];
            #pragma unroll
            for (int i = 0; i < 8; ++i) a[i]  = As[kk][ty * 8 + i];
            #pragma unroll
            for (int j = 0; j < 8; ++j) bb[j] = Bs[kk][tx * 8 + j];
            #pragma unroll
            for (int i = 0; i < 8; ++i)
                #pragma unroll
                for (int j = 0; j < 8; ++j)
                    acc[i][j] += a[i] * bb[j];
        }
        __syncthreads();
    }

    float* E = g_E + (size_t)b * N_ * N_;
    #pragma unroll
    for (int i = 0; i < 8; ++i)
        #pragma unroll
        for (int j = 0; j < 8; ++j)
            E[(size_t)(j0 + ty * 8 + i) * N_ + k0c + tx * 8 + j] = acc[i][j];
}

// ---------------------------------------------------------------------------
// Row softmax in-place on g_E. One block per (b, j) row of 4096.
// ---------------------------------------------------------------------------
__global__ __launch_bounds__(256) void softmax_kernel()
{
    const int b = blockIdx.y;
    const int j = blockIdx.x;
    float* row = g_E + ((size_t)b * N_ + j) * N_;
    const int tid = threadIdx.x;

    float v[16];
    float m = -CUDART_INF_F;
    #pragma unroll
    for (int i = 0; i < 16; ++i) { v[i] = row[tid + i * 256]; m = fmaxf(m, v[i]); }

    __shared__ float red[8];
    #pragma unroll
    for (int o = 16; o; o >>= 1) m = fmaxf(m, __shfl_xor_sync(0xffffffffu, m, o));
    if ((tid & 31) == 0) red[tid >> 5] = m;
    __syncthreads();
    {
        float t = (tid < 8) ? red[tid] : -CUDART_INF_F;
        #pragma unroll
        for (int o = 4; o; o >>= 1) t = fmaxf(t, __shfl_xor_sync(0xffffffffu, t, o));
        if (tid == 0) red[0] = t;
    }
    __syncthreads();
    m = red[0];
    __syncthreads();

    float s = 0.f;
    #pragma unroll
    for (int i = 0; i < 16; ++i) { v[i] = __expf(v[i] - m); s += v[i]; }
    #pragma unroll
    for (int o = 16; o; o >>= 1) s += __shfl_xor_sync(0xffffffffu, s, o);
    if ((tid & 31) == 0) red[tid >> 5] = s;
    __syncthreads();
    {
        float t = (tid < 8) ? red[tid] : 0.f;
        #pragma unroll
        for (int o = 4; o; o >>= 1) t += __shfl_xor_sync(0xffffffffu, t, o);
        if (tid == 0) red[0] = t;
    }
    __syncthreads();
    const float inv = 1.0f / red[0];

    #pragma unroll
    for (int i = 0; i < 16; ++i) row[tid + i * 256] = v[i] * inv;
}

// ---------------------------------------------------------------------------
// attention[b][m] = mean_j corr[b][j][m]  -> written after the residual block
// ---------------------------------------------------------------------------
__global__ __launch_bounds__(256) void colmean_kernel(float* __restrict__ out)
{
    const int b = blockIdx.y;
    const int m = blockIdx.x * 256 + threadIdx.x;
    const float* E = g_E + (size_t)b * N_ * N_;
    float s = 0.f;
    #pragma unroll 8
    for (int j = 0; j < N_; ++j) s += E[(size_t)j * N_ + m];
    out[(size_t)B_ * C_ * N_ + (size_t)b * N_ + m] = s * (1.0f / N_);
}

// ---------------------------------------------------------------------------
// GEMM 3: residual.  R[c][j] = sum_k h[c][k] * corr[j][k]
// Both operands K-contiguous -> transpose tile loads.
// ---------------------------------------------------------------------------
__global__ __launch_bounds__(256) void residual_kernel(float* __restrict__ out)
{
    const int b  = blockIdx.z;
    const int j0 = blockIdx.x * 128;
    const int c0 = blockIdx.y * 128;

    const float* Hm   = g_fgh + (size_t)b * 1024 * N_ + (size_t)C_ * N_;  // rows 512..1023
    const float* Corr = g_E + (size_t)b * N_ * N_;

    __shared__ float As[8][128];
    __shared__ float Bs[8][128];

    const int tid = threadIdx.x;
    const int tx = tid & 15, ty = tid >> 4;
    const int r   = tid >> 1;
    const int k4  = (tid & 1) * 4;

    float acc[8][8] = {};

    for (int k0 = 0; k0 < N_; k0 += 8) {
        float4 av = *reinterpret_cast<const float4*>(&Hm[(size_t)(c0 + r) * N_ + k0 + k4]);
        As[k4 + 0][r] = av.x; As[k4 + 1][r] = av.y; As[k4 + 2][r] = av.z; As[k4 + 3][r] = av.w;
        float4 bv = *reinterpret_cast<const float4*>(&Corr[(size_t)(j0 + r) * N_ + k0 + k4]);
        Bs[k4 + 0][r] = bv.x; Bs[k4 + 1][r] = bv.y; Bs[k4 + 2][r] = bv.z; Bs[k4 + 3][r] = bv.w;
        __syncthreads();
        #pragma unroll
        for (int kk = 0; kk < 8; ++kk) {
            float a[8], bb[8];
            #pragma unroll
            for (int i = 0; i < 8; ++i) a[i]  = As[kk][ty * 8 + i];
            #pragma unroll
            for (int j = 0; j < 8; ++j) bb[j] = Bs[kk][tx * 8 + j];
            #pragma unroll
            for (int i = 0; i < 8; ++i)
                #pragma unroll
                for (int j = 0; j < 8; ++j)
                    acc[i][j] += a[i] * bb[j];
        }
        __syncthreads();
    }

    #pragma unroll
    for (int i = 0; i < 8; ++i)
        #pragma unroll
        for (int j = 0; j < 8; ++j)
            out[(size_t)b * C_ * N_ + (size_t)(c0 + ty * 8 + i) * N_ + j0 + tx * 8 + j] = acc[i][j];
}

// ---------------------------------------------------------------------------
extern "C" void kernel_launch(void* const* d_in, const int* in_sizes, int n_in,
                              void* d_out, int out_size)
{
    const float* x  = (const float*)d_in[0];
    const float* Wf = (const float*)d_in[1];
    const float* bf = (const float*)d_in[2];
    const float* Wg = (const float*)d_in[3];
    const float* bg = (const float*)d_in[4];
    const float* Wh = (const float*)d_in[5];
    const float* bh = (const float*)d_in[6];
    float* out = (float*)d_out;

    proj_kernel<<<dim3(32, 8, B_), 256>>>(x, Wf, bf, Wg, bg, Wh, bh);
    energy_kernel<<<dim3(32, 32, B_), 256>>>();
    softmax_kernel<<<dim3(N_, B_), 256>>>();
    colmean_kernel<<<dim3(N_ / 256, B_), 256>>>(out);
    residual_kernel<<<dim3(32, 4, B_), 256>>>(out);
}

// round 4
// speedup vs baseline: 2.5189x; 2.5189x over previous
#include <cuda_runtime.h>
#include <math_constants.h>
#include <cstdint>

#define B_  4
#define C_  512
#define HC_ 256
#define N_  4096

// ---------------------------------------------------------------------------
// Device scratch
// ---------------------------------------------------------------------------
__device__ float g_xt[(size_t)B_ * N_ * C_];    // x^T: [b][n][c]
__device__ float g_ft[(size_t)B_ * N_ * HC_];   // f^T: [b][n][hc]
__device__ float g_gt[(size_t)B_ * N_ * HC_];   // g^T: [b][n][hc]
__device__ float g_h [(size_t)B_ * C_ * N_];    // h:   [b][c][n]
__device__ float g_E [(size_t)B_ * N_ * N_];    // energy / correlation [b][j][k]
__device__ float g_part[(size_t)B_ * 32 * N_];  // colmean partials

// ---------------------------------------------------------------------------
// Helpers (baseline PTX only — ptxas targets sm_103, no 'a'-gated instrs)
// ---------------------------------------------------------------------------
__device__ __forceinline__ uint32_t su32(const void* p) {
    uint32_t a;
    asm("{ .reg .u64 t; cvta.to.shared.u64 t, %1; cvt.u32.u64 %0, t; }" : "=r"(a) : "l"(p));
    return a;
}
__device__ __forceinline__ void cp_async16(uint32_t dst, const void* src) {
    asm volatile("cp.async.cg.shared.global [%0], [%1], 16;" :: "r"(dst), "l"(src) : "memory");
}
__device__ __forceinline__ void cp_commit() {
    asm volatile("cp.async.commit_group;" ::: "memory");
}
__device__ __forceinline__ void cp_wait0() {
    asm volatile("cp.async.wait_group 0;" ::: "memory");
}
__device__ __forceinline__ uint32_t f2tf(float f) {
    uint32_t r;
    asm("cvt.rna.tf32.f32 %0, %1;" : "=r"(r) : "f"(f));
    return r;
}
// 3xTF32 split: v = hi + lo with both tf32-representable (hi,lo are fp32 bit patterns)
__device__ __forceinline__ void split_tf(float v, uint32_t& hi, uint32_t& lo) {
    hi = f2tf(v);
    lo = f2tf(v - __uint_as_float(hi));
}
__device__ __forceinline__ void mma_tf32(float* d, const uint32_t* a, const uint32_t* b) {
    asm volatile(
        "mma.sync.aligned.m16n8k8.row.col.f32.tf32.tf32.f32 "
        "{%0,%1,%2,%3}, {%4,%5,%6,%7}, {%8,%9}, {%0,%1,%2,%3};"
        : "+f"(d[0]), "+f"(d[1]), "+f"(d[2]), "+f"(d[3])
        : "r"(a[0]), "r"(a[1]), "r"(a[2]), "r"(a[3]), "r"(b[0]), "r"(b[1]));
}

// smem float-index with XOR swizzle: row stride 32 floats (128B), k ^ (row&7)*4
#define SWZ(r, k) (((r) * 32) + ((k) ^ (((r) & 7) * 4)))

extern __shared__ float dynsm_f[];

// ---------------------------------------------------------------------------
// GEMM core: D[128 x 128] += A[128 x K] @ B[128 x K]^T  (3xTF32 HMMA, fp32 acc)
// A rows are M (K-contig, stride lda); B rows are N (K-contig, stride ldb).
// Dynamic smem: 2 stages x (A 16KB + B 16KB) = 64KB.
// 8 warps: wr = warp>>2 (2 row groups of 64), wc = warp&3 (4 col groups of 32).
// ---------------------------------------------------------------------------
__device__ __forceinline__ void gemm_core(
    const float* __restrict__ A, int lda,
    const float* __restrict__ Bm, int ldb,
    int nK, float acc[4][4][4])
{
    float* sm = dynsm_f;
    const int tid  = threadIdx.x;
    const int lr   = tid >> 3;         // 0..31
    const int lc4  = (tid & 7) * 4;    // 0,4,...,28
    const int lane = tid & 31, warp = tid >> 5;
    const int wr = warp >> 2, wc = warp & 3;
    const int g = lane >> 2, tg = lane & 3;

    auto issue = [&](int s, int kt) {
        const int k0 = kt * 32;
        float* sa = sm + s * 8192;
        float* sb = sa + 4096;
        #pragma unroll
        for (int p = 0; p < 4; ++p) {
            const int r = p * 32 + lr;
            cp_async16(su32(&sa[SWZ(r, lc4)]), &A [(size_t)r * lda + k0 + lc4]);
            cp_async16(su32(&sb[SWZ(r, lc4)]), &Bm[(size_t)r * ldb + k0 + lc4]);
        }
        cp_commit();
    };

    issue(0, 0);

    for (int kt = 0; kt < nK; ++kt) {
        const int s = kt & 1;
        cp_wait0();
        __syncthreads();
        if (kt + 1 < nK) issue(s ^ 1, kt + 1);

        const float* sa = sm + s * 8192;
        const float* sb = sa + 4096;
        #pragma unroll
        for (int k8 = 0; k8 < 4; ++k8) {
            const int kq = k8 * 8 + tg;
            uint32_t afh[4][4], afl[4][4], bfh[4][2], bfl[4][2];
            #pragma unroll
            for (int am = 0; am < 4; ++am) {
                const int r = wr * 64 + am * 16 + g;
                split_tf(sa[SWZ(r,     kq)],     afh[am][0], afl[am][0]);
                split_tf(sa[SWZ(r + 8, kq)],     afh[am][1], afl[am][1]);
                split_tf(sa[SWZ(r,     kq + 4)], afh[am][2], afl[am][2]);
                split_tf(sa[SWZ(r + 8, kq + 4)], afh[am][3], afl[am][3]);
            }
            #pragma unroll
            for (int bn = 0; bn < 4; ++bn) {
                const int rb = wc * 32 + bn * 8 + g;
                split_tf(sb[SWZ(rb, kq)],     bfh[bn][0], bfl[bn][0]);
                split_tf(sb[SWZ(rb, kq + 4)], bfh[bn][1], bfl[bn][1]);
            }
            // pass 1: hi * hi
            #pragma unroll
            for (int am = 0; am < 4; ++am)
                #pragma unroll
                for (int bn = 0; bn < 4; ++bn)
                    mma_tf32(acc[am][bn], afh[am], bfh[bn]);
            // pass 2: hi * lo
            #pragma unroll
            for (int am = 0; am < 4; ++am)
                #pragma unroll
                for (int bn = 0; bn < 4; ++bn)
                    mma_tf32(acc[am][bn], afh[am], bfl[bn]);
            // pass 3: lo * hi
            #pragma unroll
            for (int am = 0; am < 4; ++am)
                #pragma unroll
                for (int bn = 0; bn < 4; ++bn)
                    mma_tf32(acc[am][bn], afl[am], bfh[bn]);
        }
    }
}

// Epilogue: Out[r][c] = acc (+ bias_col[c]) (+ bias_row[r]); Out pre-offset to tile.
__device__ __forceinline__ void epi_store(
    float acc[4][4][4], float* __restrict__ Out, int ld,
    const float* __restrict__ bias_col, const float* __restrict__ bias_row)
{
    const int lane = threadIdx.x & 31, warp = threadIdx.x >> 5;
    const int wr = warp >> 2, wc = warp & 3;
    const int g = lane >> 2, tg = lane & 3;
    #pragma unroll
    for (int am = 0; am < 4; ++am) {
        const int r = wr * 64 + am * 16 + g;
        const float br0 = bias_row ? bias_row[r]     : 0.f;
        const float br1 = bias_row ? bias_row[r + 8] : 0.f;
        #pragma unroll
        for (int bn = 0; bn < 4; ++bn) {
            const int c = wc * 32 + bn * 8 + tg * 2;
            const float b0 = bias_col ? bias_col[c]     : 0.f;
            const float b1 = bias_col ? bias_col[c + 1] : 0.f;
            float2 v0 = { acc[am][bn][0] + b0 + br0, acc[am][bn][1] + b1 + br0 };
            float2 v1 = { acc[am][bn][2] + b0 + br1, acc[am][bn][3] + b1 + br1 };
            *reinterpret_cast<float2*>(&Out[(size_t)r       * ld + c]) = v0;
            *reinterpret_cast<float2*>(&Out[(size_t)(r + 8) * ld + c]) = v1;
        }
    }
}

// ---------------------------------------------------------------------------
// Kernels
// ---------------------------------------------------------------------------
__global__ __launch_bounds__(256) void transpose_x_kernel(const float* __restrict__ x)
{
    __shared__ float t[32][33];
    const int b = blockIdx.z, n0 = blockIdx.x * 32, c0 = blockIdx.y * 32;
    const int tx = threadIdx.x, ty = threadIdx.y;
    const float* X = x + (size_t)b * C_ * N_;
    float* XT = g_xt + (size_t)b * N_ * C_;
    #pragma unroll
    for (int i = 0; i < 4; ++i)
        t[ty + i * 8][tx] = X[(size_t)(c0 + ty + i * 8) * N_ + n0 + tx];
    __syncthreads();
    #pragma unroll
    for (int i = 0; i < 4; ++i)
        XT[(size_t)(n0 + ty + i * 8) * C_ + c0 + tx] = t[tx][ty + i * 8];
}

// f^T / g^T:  D[n][o] = xt[n][:] . W[o][:]   -> row-major write to ft/gt
__global__ __launch_bounds__(256) void projfg_kernel(
    const float* __restrict__ Wf, const float* __restrict__ bf,
    const float* __restrict__ Wg, const float* __restrict__ bg)
{
    const int b = blockIdx.z, n0 = blockIdx.x * 128, ot = blockIdx.y;
    const float* A = g_xt + ((size_t)b * N_ + n0) * C_;
    const float* W; const float* bias; float* Out; int o0;
    if (ot < 2) { W = Wf + (size_t)(ot * 128) * C_;       bias = bf + ot * 128;       Out = g_ft + (size_t)b * N_ * HC_; o0 = ot * 128; }
    else        { W = Wg + (size_t)((ot - 2) * 128) * C_; bias = bg + (ot - 2) * 128; Out = g_gt + (size_t)b * N_ * HC_; o0 = (ot - 2) * 128; }

    float acc[4][4][4] = {};
    gemm_core(A, C_, W, C_, C_ / 32, acc);
    epi_store(acc, Out + (size_t)n0 * HC_ + o0, HC_, bias, nullptr);
}

// h:  D[c][n] = Wh[c][:] . xt[n][:]   -> row-major write to g_h
__global__ __launch_bounds__(256) void projh_kernel(
    const float* __restrict__ Wh, const float* __restrict__ bh)
{
    const int b = blockIdx.z, n0 = blockIdx.x * 128, c0 = blockIdx.y * 128;
    const float* A = Wh + (size_t)c0 * C_;
    const float* Bm = g_xt + ((size_t)b * N_ + n0) * C_;

    float acc[4][4][4] = {};
    gemm_core(A, C_, Bm, C_, C_ / 32, acc);
    epi_store(acc, g_h + (size_t)b * C_ * N_ + (size_t)c0 * N_ + n0, N_, nullptr, bh + c0);
}

// energy: D[j][k] = ft[j][:] . gt[k][:]
__global__ __launch_bounds__(256) void energy_kernel()
{
    const int b = blockIdx.z, k0 = blockIdx.x * 128, j0 = blockIdx.y * 128;
    const float* A  = g_ft + ((size_t)b * N_ + j0) * HC_;
    const float* Bm = g_gt + ((size_t)b * N_ + k0) * HC_;

    float acc[4][4][4] = {};
    gemm_core(A, HC_, Bm, HC_, HC_ / 32, acc);
    epi_store(acc, g_E + (size_t)b * N_ * N_ + (size_t)j0 * N_ + k0, N_, nullptr, nullptr);
}

// residual: D[c][j] = h[c][:] . corr[j][:]
__global__ __launch_bounds__(256) void residual_kernel(float* __restrict__ out)
{
    const int b = blockIdx.z, j0 = blockIdx.x * 128, c0 = blockIdx.y * 128;
    const float* A  = g_h + (size_t)b * C_ * N_ + (size_t)c0 * N_;
    const float* Bm = g_E + (size_t)b * N_ * N_ + (size_t)j0 * N_;

    float acc[4][4][4] = {};
    gemm_core(A, N_, Bm, N_, N_ / 32, acc);
    epi_store(acc, out + (size_t)b * C_ * N_ + (size_t)c0 * N_ + j0, N_, nullptr, nullptr);
}

__global__ __launch_bounds__(256) void softmax_kernel()
{
    const int b = blockIdx.y;
    const int j = blockIdx.x;
    float* row = g_E + ((size_t)b * N_ + j) * N_;
    const int tid = threadIdx.x;

    float v[16];
    float m = -CUDART_INF_F;
    #pragma unroll
    for (int i = 0; i < 16; ++i) { v[i] = row[tid + i * 256]; m = fmaxf(m, v[i]); }

    __shared__ float red[8];
    #pragma unroll
    for (int o = 16; o; o >>= 1) m = fmaxf(m, __shfl_xor_sync(0xffffffffu, m, o));
    if ((tid & 31) == 0) red[tid >> 5] = m;
    __syncthreads();
    {
        float t = (tid < 8) ? red[tid] : -CUDART_INF_F;
        #pragma unroll
        for (int o = 4; o; o >>= 1) t = fmaxf(t, __shfl_xor_sync(0xffffffffu, t, o));
        if (tid == 0) red[0] = t;
    }
    __syncthreads();
    m = red[0];
    __syncthreads();

    float s = 0.f;
    #pragma unroll
    for (int i = 0; i < 16; ++i) { v[i] = __expf(v[i] - m); s += v[i]; }
    #pragma unroll
    for (int o = 16; o; o >>= 1) s += __shfl_xor_sync(0xffffffffu, s, o);
    if ((tid & 31) == 0) red[tid >> 5] = s;
    __syncthreads();
    {
        float t = (tid < 8) ? red[tid] : 0.f;
        #pragma unroll
        for (int o = 4; o; o >>= 1) t += __shfl_xor_sync(0xffffffffu, t, o);
        if (tid == 0) red[0] = t;
    }
    __syncthreads();
    const float inv = 1.0f / red[0];

    #pragma unroll
    for (int i = 0; i < 16; ++i) row[tid + i * 256] = v[i] * inv;
}

__global__ __launch_bounds__(256) void colmean_part_kernel()
{
    const int b = blockIdx.z, jb = blockIdx.y;
    const int col = blockIdx.x * 256 + threadIdx.x;
    const float* E = g_E + (size_t)b * N_ * N_ + (size_t)jb * 128 * N_;
    float s = 0.f;
    #pragma unroll 8
    for (int j = 0; j < 128; ++j) s += E[(size_t)j * N_ + col];
    g_part[((size_t)b * 32 + jb) * N_ + col] = s;
}

__global__ __launch_bounds__(256) void colmean_final_kernel(float* __restrict__ out)
{
    const int b = blockIdx.y;
    const int col = blockIdx.x * 256 + threadIdx.x;
    float s = 0.f;
    #pragma unroll
    for (int p = 0; p < 32; ++p) s += g_part[((size_t)b * 32 + p) * N_ + col];
    out[(size_t)B_ * C_ * N_ + (size_t)b * N_ + col] = s * (1.0f / N_);
}

// ---------------------------------------------------------------------------
extern "C" void kernel_launch(void* const* d_in, const int* in_sizes, int n_in,
                              void* d_out, int out_size)
{
    const float* x  = (const float*)d_in[0];
    const float* Wf = (const float*)d_in[1];
    const float* bf = (const float*)d_in[2];
    const float* Wg = (const float*)d_in[3];
    const float* bg = (const float*)d_in[4];
    const float* Wh = (const float*)d_in[5];
    const float* bh = (const float*)d_in[6];
    float* out = (float*)d_out;

    const int SMEM = 65536;  // 2 stages x (16KB A + 16KB B)
    cudaFuncSetAttribute(projfg_kernel,   cudaFuncAttributeMaxDynamicSharedMemorySize, SMEM);
    cudaFuncSetAttribute(projh_kernel,    cudaFuncAttributeMaxDynamicSharedMemorySize, SMEM);
    cudaFuncSetAttribute(energy_kernel,   cudaFuncAttributeMaxDynamicSharedMemorySize, SMEM);
    cudaFuncSetAttribute(residual_kernel, cudaFuncAttributeMaxDynamicSharedMemorySize, SMEM);

    transpose_x_kernel<<<dim3(N_ / 32, C_ / 32, B_), dim3(32, 8)>>>(x);
    projfg_kernel<<<dim3(32, 4, B_), 256, SMEM>>>(Wf, bf, Wg, bg);
    projh_kernel<<<dim3(32, 4, B_), 256, SMEM>>>(Wh, bh);
    energy_kernel<<<dim3(32, 32, B_), 256, SMEM>>>();
    softmax_kernel<<<dim3(N_, B_), 256>>>();
    colmean_part_kernel<<<dim3(16, 32, B_), 256>>>();
    colmean_final_kernel<<<dim3(16, B_), 256>>>(out);
    residual_kernel<<<dim3(32, 4, B_), 256, SMEM>>>(out);
}